// round 1
// baseline (speedup 1.0000x reference)
#include <cuda_runtime.h>
#include <cuda_bf16.h>

// Scratch (no allocations allowed -> __device__ globals)
__device__ float2 g_v[4][4096];   // 4 columns of the shared circuit unitary
__device__ float2 g_G[16];        // 4x4 Hermitian Gram matrix (row-major)

__device__ __forceinline__ float2 cmul(float2 a, float2 b) {
    return make_float2(a.x * b.x - a.y * b.y, a.x * b.y + a.y * b.x);
}
__device__ __forceinline__ float2 cadd(float2 a, float2 b) {
    return make_float2(a.x + b.x, a.y + b.y);
}

// ---------------------------------------------------------------------------
// K1: simulate the weight-only circuit on basis state k_j, j = (b0<<1)|b1,
//     k_j = b0*2048 + b1*1024   (wire 0 = MSB, 12 qubits)
// One block per basis column. State in shared memory (4096 complex = 32KB).
// ---------------------------------------------------------------------------
__global__ __launch_bounds__(1024) void sim_columns_kernel(const float* __restrict__ weights) {
    __shared__ float2 psi[4096];
    __shared__ float2 rot[96][4];   // 96 Rot gates, 2x2 each

    const int tid = threadIdx.x;
    const int j = blockIdx.x;
    const int b0 = (j >> 1) & 1, b1 = j & 1;
    const int kj = b0 * 2048 + b1 * 1024;

    for (int i = tid; i < 4096; i += 1024)
        psi[i] = make_float2(i == kj ? 1.0f : 0.0f, 0.0f);

    // Precompute all 96 Rot matrices: Rot(phi,theta,omega) = RZ(om) RY(th) RZ(phi)
    if (tid < 96) {
        float phi = weights[tid * 3 + 0];
        float th  = weights[tid * 3 + 1];
        float om  = weights[tid * 3 + 2];
        float st, ct; sincosf(th * 0.5f, &st, &ct);
        float sp, cp; sincosf((phi + om) * 0.5f, &sp, &cp);
        float sm, cm; sincosf((phi - om) * 0.5f, &sm, &cm);
        rot[tid][0] = make_float2( cp * ct, -sp * ct);  // e^{-i(phi+om)/2} c
        rot[tid][1] = make_float2(-cm * st, -sm * st);  // -e^{+i(phi-om)/2} s
        rot[tid][2] = make_float2( cm * st, -sm * st);  // e^{-i(phi-om)/2} s
        rot[tid][3] = make_float2( cp * ct,  sp * ct);  // e^{+i(phi+om)/2} c
    }
    __syncthreads();

    for (int l = 0; l < 8; l++) {
        // 12 single-qubit Rot gates
        for (int w = 0; w < 12; w++) {
            const int g = l * 12 + w;
            const float2 u00 = rot[g][0], u01 = rot[g][1];
            const float2 u10 = rot[g][2], u11 = rot[g][3];
            const int p = 11 - w;            // bit position of wire w
            const int mask = 1 << p;
            #pragma unroll 2
            for (int t = tid; t < 2048; t += 1024) {
                int i0 = ((t >> p) << (p + 1)) | (t & (mask - 1));
                int i1 = i0 | mask;
                float2 a0 = psi[i0], a1 = psi[i1];
                psi[i0] = cadd(cmul(u00, a0), cmul(u01, a1));
                psi[i1] = cadd(cmul(u10, a0), cmul(u11, a1));
            }
            __syncthreads();
        }
        // 11 adjacent CNOTs: control c (bit pc), target c+1 (bit pt = pc-1)
        for (int c = 0; c < 11; c++) {
            const int pt = 10 - c;           // target bit position
            // enumerate the 1024 indices with ctrl bit = 1, target bit = 0
            if (tid < 1024) {
                int low  = tid & ((1 << pt) - 1);
                int high = tid >> pt;
                int i0 = (high << (pt + 2)) | (2 << pt) | low;  // ctrl=1, tgt=0
                int i1 = i0 | (1 << pt);                        // ctrl=1, tgt=1
                float2 tmp = psi[i0]; psi[i0] = psi[i1]; psi[i1] = tmp;
            }
            __syncthreads();
        }
    }

    for (int i = tid; i < 4096; i += 1024)
        g_v[j][i] = psi[i];
}

// ---------------------------------------------------------------------------
// K2: G[j][k] = sum_idx s(idx) * v_j[idx] * conj(v_k[idx]),
//     s(idx) = sum_w head_w[w] * (1 - 2*bit_w(idx)).  One block, 256 threads.
// ---------------------------------------------------------------------------
__global__ __launch_bounds__(256) void gram_kernel(const float* __restrict__ head_w) {
    const int tid = threadIdx.x;
    float hw[12];
    #pragma unroll
    for (int w = 0; w < 12; w++) hw[w] = head_w[w];

    float2 acc[4][4];
    #pragma unroll
    for (int a = 0; a < 4; a++)
        #pragma unroll
        for (int b = 0; b < 4; b++) acc[a][b] = make_float2(0.f, 0.f);

    for (int idx = tid; idx < 4096; idx += 256) {
        float s = 0.f;
        #pragma unroll
        for (int w = 0; w < 12; w++)
            s += ((idx >> (11 - w)) & 1) ? -hw[w] : hw[w];
        float2 v[4];
        #pragma unroll
        for (int a = 0; a < 4; a++) v[a] = g_v[a][idx];
        #pragma unroll
        for (int a = 0; a < 4; a++)
            #pragma unroll
            for (int b = 0; b < 4; b++) {
                // v[a] * conj(v[b])
                float pr = v[a].x * v[b].x + v[a].y * v[b].y;
                float pi = v[a].y * v[b].x - v[a].x * v[b].y;
                acc[a][b].x += s * pr;
                acc[a][b].y += s * pi;
            }
    }

    // Block reduction of 32 scalar components
    __shared__ float red[8][32];
    float* flat = reinterpret_cast<float*>(acc);
    const int lane = tid & 31, warp = tid >> 5;
    #pragma unroll
    for (int comp = 0; comp < 32; comp++) {
        float v = flat[comp];
        #pragma unroll
        for (int off = 16; off; off >>= 1)
            v += __shfl_down_sync(0xffffffff, v, off);
        if (lane == 0) red[warp][comp] = v;
    }
    __syncthreads();
    if (tid < 32) {
        float v = 0.f;
        #pragma unroll
        for (int w = 0; w < 8; w++) v += red[w][tid];
        reinterpret_cast<float*>(g_G)[tid] = v;
    }
}

// ---------------------------------------------------------------------------
// K3: per-sample output. c_j from RX(θ0)|0> ⊗ RY(θ1)|0>:
//   c_00 = cx*cy, c_01 = cx*sy, c_10 = -i*sx*cy, c_11 = -i*sx*sy
// out = Re(c† G c) + bias  (conj(c_k) pairs with c_j via G[j][k])
// ---------------------------------------------------------------------------
__global__ __launch_bounds__(256) void output_kernel(const float* __restrict__ sb,
                                                     const float* __restrict__ head_b,
                                                     float* __restrict__ out, int B) {
    int i = blockIdx.x * blockDim.x + threadIdx.x;
    if (i >= B) return;
    float t0 = sb[i * 8 + 0], t1 = sb[i * 8 + 1];
    float s0, c0, s1, c1;
    sincosf(t0 * 0.5f, &s0, &c0);
    sincosf(t1 * 0.5f, &s1, &c1);
    float2 c[4];
    c[0] = make_float2(c0 * c1, 0.f);
    c[1] = make_float2(c0 * s1, 0.f);
    c[2] = make_float2(0.f, -s0 * c1);
    c[3] = make_float2(0.f, -s0 * s1);

    float res = head_b[0];
    #pragma unroll
    for (int j = 0; j < 4; j++)
        #pragma unroll
        for (int k = 0; k < 4; k++) {
            // cc = c[j] * conj(c[k])
            float ccr = c[j].x * c[k].x + c[j].y * c[k].y;
            float cci = c[j].y * c[k].x - c[j].x * c[k].y;
            float2 g = g_G[j * 4 + k];
            res += ccr * g.x - cci * g.y;   // Re(cc * g)
        }
    out[i] = res;
}

extern "C" void kernel_launch(void* const* d_in, const int* in_sizes, int n_in,
                              void* d_out, int out_size) {
    const float* state_batch = (const float*)d_in[0];  // (B, 8)
    const float* weights     = (const float*)d_in[1];  // (8, 12, 3)
    const float* head_w      = (const float*)d_in[2];  // (1, 12)
    const float* head_b      = (const float*)d_in[3];  // (1,)
    float* out = (float*)d_out;
    const int B = in_sizes[0] / 8;

    sim_columns_kernel<<<4, 1024>>>(weights);
    gram_kernel<<<1, 256>>>(head_w);
    output_kernel<<<(B + 255) / 256, 256>>>(state_batch, head_b, out, B);
}

// round 2
// speedup vs baseline: 1.4026x; 1.4026x over previous
#include <cuda_runtime.h>
#include <cuda_bf16.h>

// Scratch (no allocations allowed -> __device__ globals)
__device__ float2 g_v[4][4096];   // 4 columns of the circuit unitary (permuted storage)
__device__ float2 g_G[16];        // 4x4 Hermitian Gram matrix (row-major)

// ---------------------------------------------------------------------------
// GF(2) bookkeeping for the fused CNOT cascades.
// CNOT cascade (ctrl w, tgt w+1, w=0..10) permutes basis states by M (prefix
// XOR over wires). We never permute data; storage a[x] represents psi[y] with
// x = T y, T = (M^-1)^l after l cascades. A Rot gate on wire w then pairs
// storage indices (x, x^m) with m = column w of T, branch selected by
// parity(x & r), r = row w of M^l. Bit position of wire w is 11-w.
// (M^-1)^l = sum_k C(l,k) S^k ; M^l = sum_k C(k+l-1,l-1) S^k  (mod 2)
// ---------------------------------------------------------------------------
__host__ __device__ constexpr int mask_lw(int l, int w) {
    int m = 0;
    for (int k = 0; k <= l; k++)
        if ((k & ~l) == 0 && w + k <= 11) m |= 1 << (11 - (w + k));
    return m;
}
__host__ __device__ constexpr int rsel_lw(int l, int w) {
    if (l == 0) return 1 << (11 - w);
    int r = 0;
    for (int k = 0; k <= w; k++)
        if (((l - 1) & ~(k + l - 1)) == 0) r |= 1 << (11 - (w - k));
    return r;
}

struct SimSmem {
    float2 rot[96][4];   // per-gate 2x2 matrices
    float2 buf[4096];    // staging for cross-warp gates (bank-swizzled layout)
};

// Bank-conflict-free staging layout: buf index = (local<<8) | thread
__device__ __forceinline__ int bufidx(int x) { return ((x & 15) << 8) | (x >> 4); }

// ---------------------------------------------------------------------------
// One Rot gate at (layer L, wire W). State: A[16] registers per thread,
// storage index x = t*16 + l  (t: 8 thread bits = 3 warp + 5 lane, l: 4 local)
// ---------------------------------------------------------------------------
template<int L, int W>
__device__ __forceinline__ void apply_gate(float2 A[16], SimSmem* sm, int t) {
    constexpr int m    = mask_lw(L, W);
    constexpr int r    = rsel_lw(L, W);
    constexpr int mloc = m & 15;
    constexpr int mthr = m >> 4;
    constexpr int rloc = r & 15;
    constexpr int rthr = r >> 4;

    const float2 u00 = sm->rot[L * 12 + W][0];
    const float2 u01 = sm->rot[L * 12 + W][1];
    const float2 u10 = sm->rot[L * 12 + W][2];
    const float2 u11 = sm->rot[L * 12 + W][3];

    // branch bit b(x) = parity(x & r) = pt ^ parity(l & rloc)
    const bool pt = (__popc(t & rthr) & 1) != 0;
    // self/partner coefficients for the two compile-time local-parity classes
    const float2 d00 = pt ? u11 : u00;   // q=0: self
    const float2 d01 = pt ? u10 : u01;   // q=0: partner
    const float2 d11 = pt ? u00 : u11;   // q=1: self
    const float2 d10 = pt ? u01 : u10;   // q=1: partner

    float2 P[16];
    if constexpr (mthr == 0) {
        // pure-register gate
        #pragma unroll
        for (int l = 0; l < 16; l++) P[l] = A[l ^ mloc];
    } else if constexpr (mthr < 32) {
        // lane-exchange gate (no barrier)
        #pragma unroll
        for (int l = 0; l < 16; l++) {
            float2 v = A[l ^ mloc];
            P[l].x = __shfl_xor_sync(0xffffffffu, v.x, mthr);
            P[l].y = __shfl_xor_sync(0xffffffffu, v.y, mthr);
        }
    } else {
        // cross-warp gate via shared memory
        __syncthreads();   // prior readers of buf are done
        #pragma unroll
        for (int l = 0; l < 16; l++) sm->buf[bufidx(t * 16 + l)] = A[l];
        __syncthreads();
        #pragma unroll
        for (int l = 0; l < 16; l++) P[l] = sm->buf[bufidx((t * 16 + l) ^ m)];
    }

    #pragma unroll
    for (int l = 0; l < 16; l++) {
        const bool q = (__popc(l & rloc) & 1) != 0;  // compile-time after unroll
        const float2 cs = q ? d11 : d00;
        const float2 cp = q ? d10 : d01;
        const float2 a = A[l], p = P[l];
        float nx = cs.x * a.x - cs.y * a.y + cp.x * p.x - cp.y * p.y;
        float ny = cs.x * a.y + cs.y * a.x + cp.x * p.y + cp.y * p.x;
        A[l] = make_float2(nx, ny);
    }
}

template<int L, int W>
__device__ __forceinline__ void run_gates(float2 A[16], SimSmem* sm, int t) {
    apply_gate<L, W>(A, sm, t);
    if constexpr (W < 11)      run_gates<L, W + 1>(A, sm, t);
    else if constexpr (L < 7)  run_gates<L + 1, 0>(A, sm, t);
}

// ---------------------------------------------------------------------------
// K1: 4 blocks (one basis column each), 256 threads, state in registers.
// ---------------------------------------------------------------------------
__global__ __launch_bounds__(256, 1) void sim_columns_kernel(const float* __restrict__ weights) {
    __shared__ SimSmem sm;
    const int t = threadIdx.x;
    const int j = blockIdx.x;

    if (t < 96) {
        float phi = weights[t * 3 + 0];
        float th  = weights[t * 3 + 1];
        float om  = weights[t * 3 + 2];
        float st, ct; sincosf(th * 0.5f, &st, &ct);
        float sp, cp; sincosf((phi + om) * 0.5f, &sp, &cp);
        float sd, cd; sincosf((phi - om) * 0.5f, &sd, &cd);
        sm.rot[t][0] = make_float2( cp * ct, -sp * ct);
        sm.rot[t][1] = make_float2(-cd * st, -sd * st);
        sm.rot[t][2] = make_float2( cd * st, -sd * st);
        sm.rot[t][3] = make_float2( cp * ct,  sp * ct);
    }
    __syncthreads();

    // init |kj>: kj = b0*2048 + b1*1024  (wire0=b0 -> bit11, wire1=b1 -> bit10)
    const int kt = ((j >> 1) & 1) * 128 + (j & 1) * 64;  // thread part of kj
    float2 A[16];
    #pragma unroll
    for (int l = 0; l < 16; l++)
        A[l] = make_float2((t == kt && l == 0) ? 1.0f : 0.0f, 0.0f);

    run_gates<0, 0>(A, &sm, t);

    #pragma unroll
    for (int l = 0; l < 16; l++)
        g_v[j][t * 16 + l] = A[l];
}

// ---------------------------------------------------------------------------
// K2: G[j][k] = sum_x s(y(x)) v_j[x] conj(v_k[x]); y = M^8 x, so
//     y_w = parity(x & rsel_lw(8, w)).  One block, 1024 threads.
// ---------------------------------------------------------------------------
__global__ __launch_bounds__(1024) void gram_kernel(const float* __restrict__ head_w) {
    const int tid = threadIdx.x;
    float hw[12];
    #pragma unroll
    for (int w = 0; w < 12; w++) hw[w] = head_w[w];

    float2 acc[4][4];
    #pragma unroll
    for (int a = 0; a < 4; a++)
        #pragma unroll
        for (int b = 0; b < 4; b++) acc[a][b] = make_float2(0.f, 0.f);

    for (int idx = tid; idx < 4096; idx += 1024) {
        float s = 0.f;
        #pragma unroll
        for (int w = 0; w < 12; w++) {
            const int rm = rsel_lw(8, w);
            s += (__popc(idx & rm) & 1) ? -hw[w] : hw[w];
        }
        float2 v[4];
        #pragma unroll
        for (int a = 0; a < 4; a++) v[a] = g_v[a][idx];
        #pragma unroll
        for (int a = 0; a < 4; a++)
            #pragma unroll
            for (int b = 0; b < 4; b++) {
                float pr = v[a].x * v[b].x + v[a].y * v[b].y;
                float pi = v[a].y * v[b].x - v[a].x * v[b].y;
                acc[a][b].x += s * pr;
                acc[a][b].y += s * pi;
            }
    }

    __shared__ float red[32][32];
    float* flat = reinterpret_cast<float*>(acc);
    const int lane = tid & 31, warp = tid >> 5;
    #pragma unroll
    for (int comp = 0; comp < 32; comp++) {
        float v = flat[comp];
        #pragma unroll
        for (int off = 16; off; off >>= 1)
            v += __shfl_down_sync(0xffffffff, v, off);
        if (lane == 0) red[warp][comp] = v;
    }
    __syncthreads();
    if (tid < 32) {
        float v = 0.f;
        #pragma unroll
        for (int w = 0; w < 32; w++) v += red[w][tid];
        reinterpret_cast<float*>(g_G)[tid] = v;
    }
}

// ---------------------------------------------------------------------------
// K3: per-sample output. c from RX(t0) w0 (x) RY(t1) w1 applied to |00>.
// out = Re(c^H G c) + bias
// ---------------------------------------------------------------------------
__global__ __launch_bounds__(256) void output_kernel(const float* __restrict__ sb,
                                                     const float* __restrict__ head_b,
                                                     float* __restrict__ out, int B) {
    int i = blockIdx.x * blockDim.x + threadIdx.x;
    if (i >= B) return;
    float t0 = sb[i * 8 + 0], t1 = sb[i * 8 + 1];
    float s0, c0, s1, c1;
    sincosf(t0 * 0.5f, &s0, &c0);
    sincosf(t1 * 0.5f, &s1, &c1);
    float2 c[4];
    c[0] = make_float2(c0 * c1, 0.f);
    c[1] = make_float2(c0 * s1, 0.f);
    c[2] = make_float2(0.f, -s0 * c1);
    c[3] = make_float2(0.f, -s0 * s1);

    float res = head_b[0];
    #pragma unroll
    for (int j = 0; j < 4; j++)
        #pragma unroll
        for (int k = 0; k < 4; k++) {
            float ccr = c[j].x * c[k].x + c[j].y * c[k].y;
            float cci = c[j].y * c[k].x - c[j].x * c[k].y;
            float2 g = g_G[j * 4 + k];
            res += ccr * g.x - cci * g.y;
        }
    out[i] = res;
}

extern "C" void kernel_launch(void* const* d_in, const int* in_sizes, int n_in,
                              void* d_out, int out_size) {
    const float* state_batch = (const float*)d_in[0];  // (B, 8)
    const float* weights     = (const float*)d_in[1];  // (8, 12, 3)
    const float* head_w      = (const float*)d_in[2];  // (1, 12)
    const float* head_b      = (const float*)d_in[3];  // (1,)
    float* out = (float*)d_out;
    const int B = in_sizes[0] / 8;

    sim_columns_kernel<<<4, 256>>>(weights);
    gram_kernel<<<1, 1024>>>(head_w);
    output_kernel<<<(B + 255) / 256, 256>>>(state_batch, head_b, out, B);
}

// round 3
// speedup vs baseline: 1.9951x; 1.4224x over previous
#include <cuda_runtime.h>
#include <cuda_bf16.h>

typedef unsigned long long u64;

// Scratch (no allocations allowed -> __device__ globals)
__device__ float2 g_v[4][4096];   // 4 columns of the circuit unitary (natural order)
__device__ float2 g_G[16];        // 4x4 Hermitian Gram matrix

// ---------------- f32x2 packed helpers ----------------
__device__ __forceinline__ u64 pack2(float x, float y) {
    u64 u; asm("mov.b64 %0, {%1,%2};" : "=l"(u) : "f"(x), "f"(y)); return u;
}
__device__ __forceinline__ float2 unpack2(u64 u) {
    float2 v; asm("mov.b64 {%0,%1}, %2;" : "=f"(v.x), "=f"(v.y) : "l"(u)); return v;
}
__device__ __forceinline__ u64 swap2(u64 u) {
    float2 v = unpack2(u); return pack2(v.y, v.x);
}
__device__ __forceinline__ u64 fma2(u64 a, u64 b, u64 c) {
    u64 d; asm("fma.rn.f32x2 %0, %1, %2, %3;" : "=l"(d) : "l"(a), "l"(b), "l"(c)); return d;
}
__device__ __forceinline__ u64 mul2(u64 a, u64 b) {
    u64 d; asm("mul.rn.f32x2 %0, %1, %2;" : "=l"(d) : "l"(a), "l"(b)); return d;
}

// Packed per-lane gate coefficients: self (s) and off-diagonal (o) complex coeffs
struct Coef { u64 sx, sy, nsy, ox, oy, noy; };

__device__ __forceinline__ Coef makeCoef(float2 s0, float2 o0, float2 s1, float2 o1) {
    Coef c;
    c.sx  = pack2(s0.x, s1.x);
    c.sy  = pack2(s0.y, s1.y);
    c.nsy = pack2(-s0.y, -s1.y);
    c.ox  = pack2(o0.x, o1.x);
    c.oy  = pack2(o0.y, o1.y);
    c.noy = pack2(-o0.y, -o1.y);
    return c;
}

// new = s*a + o*p (complex, 2 lanes): 8 f32x2 ops
__device__ __forceinline__ void cupd(u64 X, u64 Y, u64 PX, u64 PY, const Coef& c,
                                     u64& NX, u64& NY) {
    u64 nx = mul2(c.sx, X);
    nx = fma2(c.nsy, Y, nx);
    nx = fma2(c.ox, PX, nx);
    nx = fma2(c.noy, PY, nx);
    u64 ny = mul2(c.sx, Y);
    ny = fma2(c.sy, X, ny);
    ny = fma2(c.ox, PY, ny);
    ny = fma2(c.oy, PX, ny);
    NX = nx; NY = ny;
}

// ---------------- shared memory ----------------
struct SimSmem {
    float2 rot[96][4];            // u00,u01,u10,u11 per gate
    union {
        struct { u64 X[2048]; u64 Y[2048]; } pp;  // pair-packed staging
        float2 amp[4096];                          // per-amplitude staging (perm)
    } buf;
};

// ---------------------------------------------------------------------------
// Gates. State: 8 amplitudes/thread as 4 lane-pairs: AX[i]=(re(2i),re(2i+1)),
// AY[i]=(im(2i),im(2i+1)). Global index x = (t<<3) | l,  t=threadIdx (9 bits),
// l=local (3 bits). Wire w acts on bit p = 11-w of x.
// ---------------------------------------------------------------------------

// p=0: partner = other lane of same pair; lane0 is |0> branch, lane1 is |1>.
__device__ __forceinline__ void gate_p0(u64 AX[4], u64 AY[4], const float2* u) {
    Coef C = makeCoef(u[0], u[1], u[3], u[2]);
    #pragma unroll
    for (int i = 0; i < 4; i++) {
        u64 px = swap2(AX[i]), py = swap2(AY[i]);
        cupd(AX[i], AY[i], px, py, C, AX[i], AY[i]);
    }
}

// p=1 (HS=1) or p=2 (HS=2): partner pair = i ^ HS, branch bit from pair index.
template<int HS>
__device__ __forceinline__ void gate_reg(u64 AX[4], u64 AY[4], const float2* u) {
    Coef C0 = makeCoef(u[0], u[1], u[0], u[1]);
    Coef C1 = makeCoef(u[3], u[2], u[3], u[2]);
    #pragma unroll
    for (int a = 0; a < 4; a++) {
        if (a & HS) continue;
        int b = a | HS;
        u64 nx0, ny0, nx1, ny1;
        cupd(AX[a], AY[a], AX[b], AY[b], C0, nx0, ny0);
        cupd(AX[b], AY[b], AX[a], AY[a], C1, nx1, ny1);
        AX[a] = nx0; AY[a] = ny0; AX[b] = nx1; AY[b] = ny1;
    }
}

// p in 3..7: partner in lane t ^ (1<<(p-3)); branch = that bit of t.
template<int P>
__device__ __forceinline__ void gate_lane(u64 AX[4], u64 AY[4], const float2* u, int t) {
    const int lm = 1 << (P - 3);
    const bool pt = (t >> (P - 3)) & 1;
    float2 s = pt ? u[3] : u[0];
    float2 o = pt ? u[2] : u[1];
    Coef C = makeCoef(s, o, s, o);
    #pragma unroll
    for (int i = 0; i < 4; i++) {
        float2 ax = unpack2(AX[i]), ay = unpack2(AY[i]);
        ax.x = __shfl_xor_sync(0xffffffffu, ax.x, lm);
        ax.y = __shfl_xor_sync(0xffffffffu, ax.y, lm);
        ay.x = __shfl_xor_sync(0xffffffffu, ay.x, lm);
        ay.y = __shfl_xor_sync(0xffffffffu, ay.y, lm);
        cupd(AX[i], AY[i], pack2(ax.x, ax.y), pack2(ay.x, ay.y), C, AX[i], AY[i]);
    }
}

// p in 8..11: partner in thread t ^ (1<<(p-3)) (cross-warp) via shared memory.
template<int P>
__device__ __forceinline__ void gate_smem(u64 AX[4], u64 AY[4], const float2* u,
                                          int t, SimSmem* sm) {
    __syncthreads();
    #pragma unroll
    for (int i = 0; i < 4; i++) {
        sm->buf.pp.X[(i << 9) | t] = AX[i];
        sm->buf.pp.Y[(i << 9) | t] = AY[i];
    }
    __syncthreads();
    const int tp = t ^ (1 << (P - 3));
    const bool pt = (t >> (P - 3)) & 1;
    float2 s = pt ? u[3] : u[0];
    float2 o = pt ? u[2] : u[1];
    Coef C = makeCoef(s, o, s, o);
    #pragma unroll
    for (int i = 0; i < 4; i++) {
        u64 px = sm->buf.pp.X[(i << 9) | tp];
        u64 py = sm->buf.pp.Y[(i << 9) | tp];
        cupd(AX[i], AY[i], px, py, C, AX[i], AY[i]);
    }
}

// CNOT cascade: new[y] = old[y ^ (y>>1)] (from reference _cnot_adj semantics).
__device__ __forceinline__ void perm_cnot(u64 AX[4], u64 AY[4], int t, SimSmem* sm) {
    __syncthreads();
    #pragma unroll
    for (int i = 0; i < 4; i++) {
        float2 xs = unpack2(AX[i]), ys = unpack2(AY[i]);
        sm->buf.amp[((2 * i) << 9) | t]     = make_float2(xs.x, ys.x);
        sm->buf.amp[((2 * i + 1) << 9) | t] = make_float2(xs.y, ys.y);
    }
    __syncthreads();
    #pragma unroll
    for (int i = 0; i < 4; i++) {
        int y0 = (t << 3) | (2 * i);
        int y1 = y0 | 1;
        int s0 = y0 ^ (y0 >> 1);
        int s1 = y1 ^ (y1 >> 1);
        float2 f0 = sm->buf.amp[((s0 & 7) << 9) | (s0 >> 3)];
        float2 f1 = sm->buf.amp[((s1 & 7) << 9) | (s1 >> 3)];
        AX[i] = pack2(f0.x, f1.x);
        AY[i] = pack2(f0.y, f1.y);
    }
}

// ---------------------------------------------------------------------------
// K1: 4 blocks (one basis column each), 512 threads, 8 amps/thread.
// ---------------------------------------------------------------------------
__global__ __launch_bounds__(512, 1) void sim_columns_kernel(const float* __restrict__ weights) {
    __shared__ SimSmem sm;
    const int t = threadIdx.x;
    const int j = blockIdx.x;

    if (t < 96) {
        float phi = weights[t * 3 + 0];
        float th  = weights[t * 3 + 1];
        float om  = weights[t * 3 + 2];
        float st, ct; sincosf(th * 0.5f, &st, &ct);
        float sp, cp; sincosf((phi + om) * 0.5f, &sp, &cp);
        float sd, cd; sincosf((phi - om) * 0.5f, &sd, &cd);
        sm.rot[t][0] = make_float2( cp * ct, -sp * ct);   // u00
        sm.rot[t][1] = make_float2(-cd * st, -sd * st);   // u01
        sm.rot[t][2] = make_float2( cd * st, -sd * st);   // u10
        sm.rot[t][3] = make_float2( cp * ct,  sp * ct);   // u11
    }
    __syncthreads();

    // init |kj>: kj = b0*2048 + b1*1024 -> thread kj>>3, local 0 (pair 0 lane 0)
    const int t_init = ((j >> 1) & 1) * 256 + (j & 1) * 128;
    u64 AX[4], AY[4];
    #pragma unroll
    for (int i = 0; i < 4; i++) { AX[i] = 0ull; AY[i] = 0ull; }
    if (t == t_init) AX[0] = pack2(1.0f, 0.0f);

    #pragma unroll 1
    for (int l = 0; l < 8; l++) {
        const float2 (*R)[4] = (const float2 (*)[4]) & sm.rot[l * 12];
        gate_p0(AX, AY, R[11]);               // wire 11, bit 0
        gate_reg<1>(AX, AY, R[10]);           // wire 10, bit 1
        gate_reg<2>(AX, AY, R[9]);            // wire 9,  bit 2
        gate_lane<3>(AX, AY, R[8], t);        // wire 8,  bit 3
        gate_lane<4>(AX, AY, R[7], t);
        gate_lane<5>(AX, AY, R[6], t);
        gate_lane<6>(AX, AY, R[5], t);
        gate_lane<7>(AX, AY, R[4], t);        // wire 4,  bit 7
        gate_smem<8>(AX, AY, R[3], t, &sm);   // wire 3,  bit 8
        gate_smem<9>(AX, AY, R[2], t, &sm);
        gate_smem<10>(AX, AY, R[1], t, &sm);
        gate_smem<11>(AX, AY, R[0], t, &sm);  // wire 0,  bit 11
        perm_cnot(AX, AY, t, &sm);
    }

    #pragma unroll
    for (int i = 0; i < 4; i++) {
        float2 xs = unpack2(AX[i]), ys = unpack2(AY[i]);
        g_v[j][(t << 3) | (2 * i)]     = make_float2(xs.x, ys.x);
        g_v[j][(t << 3) | (2 * i + 1)] = make_float2(xs.y, ys.y);
    }
}

// ---------------------------------------------------------------------------
// K2: G[j][k] = sum_idx s(idx) v_j[idx] conj(v_k[idx]);
//     s(idx) = sum_w head_w[w] * (1 - 2*bit_{11-w}(idx)). One block, 1024 thr.
// ---------------------------------------------------------------------------
__global__ __launch_bounds__(1024) void gram_kernel(const float* __restrict__ head_w) {
    const int tid = threadIdx.x;
    float hw[12];
    #pragma unroll
    for (int w = 0; w < 12; w++) hw[w] = head_w[w];

    float2 acc[4][4];
    #pragma unroll
    for (int a = 0; a < 4; a++)
        #pragma unroll
        for (int b = 0; b < 4; b++) acc[a][b] = make_float2(0.f, 0.f);

    for (int idx = tid; idx < 4096; idx += 1024) {
        float s = 0.f;
        #pragma unroll
        for (int w = 0; w < 12; w++)
            s += ((idx >> (11 - w)) & 1) ? -hw[w] : hw[w];
        float2 v[4];
        #pragma unroll
        for (int a = 0; a < 4; a++) v[a] = g_v[a][idx];
        #pragma unroll
        for (int a = 0; a < 4; a++)
            #pragma unroll
            for (int b = 0; b < 4; b++) {
                float pr = v[a].x * v[b].x + v[a].y * v[b].y;
                float pi = v[a].y * v[b].x - v[a].x * v[b].y;
                acc[a][b].x += s * pr;
                acc[a][b].y += s * pi;
            }
    }

    __shared__ float red[32][32];
    float* flat = reinterpret_cast<float*>(acc);
    const int lane = tid & 31, warp = tid >> 5;
    #pragma unroll
    for (int comp = 0; comp < 32; comp++) {
        float v = flat[comp];
        #pragma unroll
        for (int off = 16; off; off >>= 1)
            v += __shfl_down_sync(0xffffffff, v, off);
        if (lane == 0) red[warp][comp] = v;
    }
    __syncthreads();
    if (tid < 32) {
        float v = 0.f;
        #pragma unroll
        for (int w = 0; w < 32; w++) v += red[w][tid];
        reinterpret_cast<float*>(g_G)[tid] = v;
    }
}

// ---------------------------------------------------------------------------
// K3: per-sample output: out = Re(c^H G c) + bias, c from RX(t0)(x)RY(t1)|00>
// ---------------------------------------------------------------------------
__global__ __launch_bounds__(256) void output_kernel(const float* __restrict__ sb,
                                                     const float* __restrict__ head_b,
                                                     float* __restrict__ out, int B) {
    int i = blockIdx.x * blockDim.x + threadIdx.x;
    if (i >= B) return;
    float t0 = sb[i * 8 + 0], t1 = sb[i * 8 + 1];
    float s0, c0, s1, c1;
    sincosf(t0 * 0.5f, &s0, &c0);
    sincosf(t1 * 0.5f, &s1, &c1);
    float2 c[4];
    c[0] = make_float2(c0 * c1, 0.f);
    c[1] = make_float2(c0 * s1, 0.f);
    c[2] = make_float2(0.f, -s0 * c1);
    c[3] = make_float2(0.f, -s0 * s1);

    float res = head_b[0];
    #pragma unroll
    for (int jj = 0; jj < 4; jj++)
        #pragma unroll
        for (int k = 0; k < 4; k++) {
            float ccr = c[jj].x * c[k].x + c[jj].y * c[k].y;
            float cci = c[jj].y * c[k].x - c[jj].x * c[k].y;
            float2 g = g_G[jj * 4 + k];
            res += ccr * g.x - cci * g.y;
        }
    out[i] = res;
}

extern "C" void kernel_launch(void* const* d_in, const int* in_sizes, int n_in,
                              void* d_out, int out_size) {
    const float* state_batch = (const float*)d_in[0];  // (B, 8)
    const float* weights     = (const float*)d_in[1];  // (8, 12, 3)
    const float* head_w      = (const float*)d_in[2];  // (1, 12)
    const float* head_b      = (const float*)d_in[3];  // (1,)
    float* out = (float*)d_out;
    const int B = in_sizes[0] / 8;

    sim_columns_kernel<<<4, 512>>>(weights);
    gram_kernel<<<1, 1024>>>(head_w);
    output_kernel<<<(B + 255) / 256, 256>>>(state_batch, head_b, out, B);
}